// round 5
// baseline (speedup 1.0000x reference)
#include <cuda_runtime.h>

// Multi-scale morphological closing, [4,8,256,256] fp32 -> [4,8,4,256,256].
// closing_s = erosion_s(dilation_s(x)), separable h then v per op.
// SE_s[j] = j^2/(4*t_s), t_s = 4^s, half-width SW_s = 4*2^s, weight se_coef.
// kc = c/(4*t_s) = 4c/SW^2.
//
// Round-5: R3's proven 3-stream fork-join (mem-check clean) + chunked
// symmetric-pair inner loops for high occupancy:
//   max_j v[x+j]-kc*j^2 = max_d fmaf(-kc, d*d, max(v[x-d], v[x+d]))
// d-loop in chunks of D=8 so only ~2x16 window floats are live at once.
// Lane balance: SW32 split in two half-image chains; SW16 alone; SW8+SW4.

namespace {
constexpr int IMGS  = 32;    // B*C
constexpr int HIMGS = 16;    // images per SW32 half-chain
constexpr int H     = 256;
constexpr int W     = 256;
constexpr int NPIX  = H * W;
constexpr int NTOT  = IMGS * NPIX;
constexpr int K     = 8;     // outputs per thread
constexpr int ROWS  = 8;     // rows per block, h-pass
}

__device__ float g_t1[4][NTOT];
__device__ float g_t2[4][NTOT];

template<bool MX> __device__ __forceinline__ float mm(float a, float b) {
    return MX ? fmaxf(a, b) : fminf(a, b);
}

// ---------------------------------------------------------------------------
// Horizontal pass: block = 256 thr = 8 rows x (32 lanes x 8 outputs).
// Row staged in smem with sentinel halo; chunked sym-pair, aligned float4 LDS.
// ---------------------------------------------------------------------------
template<int SW, bool MX>
__global__ void __launch_bounds__(256, 4) hk(
    const float* __restrict__ in,
    float* __restrict__ out, long ostr,
    const float* __restrict__ sc)
{
    constexpr int PADW = W + 2 * SW;
    constexpr int D    = (SW < 8) ? SW : 8;   // chunk size (4 for SW=4)
    constexpr int NCH  = SW / D;
    constexpr int NV   = (D + K) / 4;         // float4 loads per span
    constexpr float BIG = MX ? -1e9f : 1e9f;
    const float kc  = (*sc) * (4.0f / (float)(SW * SW));
    const float kcs = MX ? -kc : kc;

    __shared__ __align__(16) float sm[ROWS][PADW];

    const int img = blockIdx.x >> 5;          // 32 row-blocks per image
    const int rb  = blockIdx.x & 31;
    const float* src = in + (long)img * NPIX + (long)(rb * ROWS) * W;

    for (int i = threadIdx.x; i < ROWS * PADW; i += 256) {
        const int r = i / PADW;
        const int p = i - r * PADW;
        const int x = p - SW;
        sm[r][p] = ((unsigned)x < (unsigned)W) ? src[r * W + x] : BIG;
    }
    __syncthreads();

    const int r    = threadIdx.x >> 5;
    const int lane = threadIdx.x & 31;
    const int x0   = lane * K;
    const float* row = &sm[r][x0 + SW];       // row[p] == v[x0 + p]

    float acc[K];
    {
        // d = 0 taps: aligned float4x2 at row[0..7]
        const float4 a = *reinterpret_cast<const float4*>(row);
        const float4 b = *reinterpret_cast<const float4*>(row + 4);
        acc[0] = a.x; acc[1] = a.y; acc[2] = a.z; acc[3] = a.w;
        acc[4] = b.x; acc[5] = b.y; acc[6] = b.z; acc[7] = b.w;
    }

    #pragma unroll
    for (int c = 0; c < NCH; ++c) {
        const int dlo = c * D + 1, dhi = (c + 1) * D;
        // la covers row[-dhi .. -dhi+4*NV-1]  (base 16B-aligned)
        // ra covers row[ c*D ..  c*D+4*NV-1] (base 16B-aligned)
        float la[4 * NV], ra[4 * NV];
        const float4* lp = reinterpret_cast<const float4*>(row - dhi);
        const float4* rp = reinterpret_cast<const float4*>(row + c * D);
        #pragma unroll
        for (int i = 0; i < NV; ++i) {
            const float4 v = lp[i];
            la[4*i+0] = v.x; la[4*i+1] = v.y; la[4*i+2] = v.z; la[4*i+3] = v.w;
        }
        #pragma unroll
        for (int i = 0; i < NV; ++i) {
            const float4 v = rp[i];
            ra[4*i+0] = v.x; ra[4*i+1] = v.y; ra[4*i+2] = v.z; ra[4*i+3] = v.w;
        }
        #pragma unroll
        for (int d = dlo; d <= dhi; ++d) {
            const float dd = (float)(d * d);              // imm
            #pragma unroll
            for (int k = 0; k < K; ++k) {
                // L[k] = row[k-d] = la[k + dhi - d]; R[k] = row[k+d] = ra[k + d - c*D]
                const float m = mm<MX>(la[k + dhi - d], ra[k + d - c * D]);
                acc[k] = mm<MX>(acc[k], fmaf(kcs, dd, m));
            }
        }
    }

    float* dst = out + (long)img * ostr + (long)(rb * ROWS + r) * W + x0;
    #pragma unroll
    for (int k = 0; k < K; ++k) dst[k] = acc[k];
}

// ---------------------------------------------------------------------------
// Vertical pass: block = 256 thr spanning full row width (coalesced),
// each thread 8 consecutive rows of one column; chunked sym-pair from gmem.
// ---------------------------------------------------------------------------
template<int SW, bool MX, bool GUARD>
__device__ __forceinline__ void vbody(
    const float* __restrict__ base, int y0, float kcs, float* acc)
{
    constexpr int D   = (SW < 8) ? SW : 8;
    constexpr int NCH = SW / D;
    constexpr float BIG = MX ? -1e9f : 1e9f;

    auto LD = [&](int dy) -> float {
        const int y = y0 + dy;
        if (GUARD && (unsigned)y >= (unsigned)H) return BIG;
        return __ldg(base + (long)y * W);
    };

    #pragma unroll
    for (int k = 0; k < K; ++k) acc[k] = LD(k);           // d = 0

    #pragma unroll
    for (int c = 0; c < NCH; ++c) {
        const int dlo = c * D + 1, dhi = (c + 1) * D;
        float L[D + K - 1], R[D + K - 1];
        #pragma unroll
        for (int i = 0; i < D + K - 1; ++i) L[i] = LD(i - dhi);
        #pragma unroll
        for (int i = 0; i < D + K - 1; ++i) R[i] = LD(i + dlo);
        #pragma unroll
        for (int d = dlo; d <= dhi; ++d) {
            const float dd = (float)(d * d);
            #pragma unroll
            for (int k = 0; k < K; ++k) {
                const float m = mm<MX>(L[k + dhi - d], R[k + d - dlo]);
                acc[k] = mm<MX>(acc[k], fmaf(kcs, dd, m));
            }
        }
    }
}

template<int SW, bool MX>
__global__ void __launch_bounds__(256, 4) vk(
    const float* __restrict__ in,
    float* __restrict__ out, long ostr,
    const float* __restrict__ sc)
{
    const float kc  = (*sc) * (4.0f / (float)(SW * SW));
    const float kcs = MX ? -kc : kc;

    const int img = blockIdx.x >> 5;          // H/K = 32 blocks per image
    const int yb  = blockIdx.x & 31;
    const int x   = threadIdx.x;
    const int y0  = yb * K;
    const float* base = in + (long)img * NPIX + x;

    float acc[K];
    if (y0 >= SW && y0 + K - 1 + SW < H)
        vbody<SW, MX, false>(base, y0, kcs, acc);
    else
        vbody<SW, MX, true >(base, y0, kcs, acc);

    float* dst = out + (long)img * ostr + (long)y0 * W + x;
    #pragma unroll
    for (int k = 0; k < K; ++k) dst[k * W] = acc[k];
}

// ---------------------------------------------------------------------------
template<int SW>
static void run_chain(cudaStream_t st, int nimgs, const float* in_p,
                      float* t1_p, float* t2_p, float* out_p, const float* sc)
{
    const int grid = nimgs * (H / ROWS);
    hk<SW, true ><<<grid, 256, 0, st>>>(in_p, t1_p, NPIX, sc);
    vk<SW, true ><<<grid, 256, 0, st>>>(t1_p, t2_p, NPIX, sc);
    hk<SW, false><<<grid, 256, 0, st>>>(t2_p, t1_p, NPIX, sc);
    vk<SW, false><<<grid, 256, 0, st>>>(t1_p, out_p, 4L * NPIX, sc);
}

// exact R3 host-object footprint (proved clean vs the mem checker)
static cudaStream_t g_st[3];
static cudaEvent_t  g_fork, g_join[3];
static bool g_ready = false;

extern "C" void kernel_launch(void* const* d_in, const int* in_sizes, int n_in,
                              void* d_out, int out_size)
{
    const float* in = (const float*)d_in[0];
    const float* sc = (const float*)d_in[1];
    if (n_in >= 2 && in_sizes[0] == 1) {      // defensive: order swap
        in = (const float*)d_in[1];
        sc = (const float*)d_in[0];
    }
    float* out = (float*)d_out;

    if (!g_ready) {
        for (int i = 0; i < 3; ++i)
            cudaStreamCreateWithFlags(&g_st[i], cudaStreamNonBlocking);
        cudaEventCreateWithFlags(&g_fork, cudaEventDisableTiming);
        for (int i = 0; i < 3; ++i)
            cudaEventCreateWithFlags(&g_join[i], cudaEventDisableTiming);
        g_ready = true;
    }

    float (*t1)[NTOT] = nullptr;
    float (*t2)[NTOT] = nullptr;
    cudaGetSymbolAddress((void**)&t1, g_t1);
    cudaGetSymbolAddress((void**)&t2, g_t2);

    cudaEventRecord(g_fork, 0);
    for (int i = 0; i < 3; ++i) cudaStreamWaitEvent(g_st[i], g_fork, 0);

    const long HOFF  = (long)HIMGS * NPIX;        // scratch offset, half 1
    const long HOFFO = (long)HIMGS * 4 * NPIX;    // output offset, half 1

    // lane 0 (capture stream): SW32 half A; lane 1: SW32 half B;
    // lane 2: SW16 full; lane 3: SW8 then SW4.
    run_chain<32>(0,       HIMGS, in,        t1[3],        t2[3],        out + 3L*NPIX,         sc);
    run_chain<32>(g_st[0], HIMGS, in + HOFF, t1[3] + HOFF, t2[3] + HOFF, out + 3L*NPIX + HOFFO, sc);
    run_chain<16>(g_st[1], IMGS,  in,        t1[2],        t2[2],        out + 2L*NPIX,         sc);
    run_chain< 8>(g_st[2], IMGS,  in,        t1[1],        t2[1],        out + 1L*NPIX,         sc);
    run_chain< 4>(g_st[2], IMGS,  in,        t1[0],        t2[0],        out + 0L*NPIX,         sc);

    for (int i = 0; i < 3; ++i) {
        cudaEventRecord(g_join[i], g_st[i]);
        cudaStreamWaitEvent(0, g_join[i], 0);
    }

    (void)out_size;
}

// round 6
// speedup vs baseline: 1.1280x; 1.1280x over previous
#include <cuda_runtime.h>

// Multi-scale morphological closing, [4,8,256,256] fp32 -> [4,8,4,256,256].
// closing_s = erosion_s(dilation_s(x)), separable h then v per op.
// SE_s[j] = j^2/(4*t_s), t_s = 4^s, half-width SW_s = 4*2^s, weight se_coef.
// kc = c/(4*t_s) = 4c/SW^2.
//
// Round-6: both passes smem-staged + chunked symmetric-pair
//   max_j v[x+j]-kc*j^2 = max_d fmaf(-kc, d*d, max(v[x-d], v[x+d]))
// (d-loop in chunks of 8: ~2x15 floats live -> 64-reg kernels, no spill,
//  chunk re-reads from SMEM not gmem). R3's proven 3-stream fork-join.

namespace {
constexpr int IMGS = 32;     // B*C
constexpr int H    = 256;
constexpr int W    = 256;
constexpr int NPIX = H * W;
constexpr int NTOT = IMGS * NPIX;
constexpr int K    = 8;      // outputs per thread
constexpr int ROWS = 8;      // rows per block, h-pass
}

__device__ float g_t1[4][NTOT];
__device__ float g_t2[4][NTOT];

template<bool MX> __device__ __forceinline__ float mm(float a, float b) {
    return MX ? fmaxf(a, b) : fminf(a, b);
}

// ---------------------------------------------------------------------------
// Horizontal pass: block = 256 thr = 8 rows x (32 lanes x 8 outputs).
// Row staged in smem with sentinel halo; chunked sym-pair, aligned float4 LDS.
// ---------------------------------------------------------------------------
template<int SW, bool MX>
__global__ void __launch_bounds__(256, 4) hk(
    const float* __restrict__ in,
    float* __restrict__ out, long ostr,
    const float* __restrict__ sc)
{
    constexpr int PADW = W + 2 * SW;
    constexpr int D    = (SW < 8) ? SW : 8;
    constexpr int NCH  = SW / D;
    constexpr int NV   = (D + K) / 4;         // float4 loads per span
    constexpr float BIG = MX ? -1e9f : 1e9f;
    const float kc  = (*sc) * (4.0f / (float)(SW * SW));
    const float kcs = MX ? -kc : kc;

    __shared__ __align__(16) float sm[ROWS][PADW];

    const int img = blockIdx.x >> 5;          // 32 row-blocks per image
    const int rb  = blockIdx.x & 31;
    const float* src = in + (long)img * NPIX + (long)(rb * ROWS) * W;

    for (int i = threadIdx.x; i < ROWS * PADW; i += 256) {
        const int r = i / PADW;
        const int p = i - r * PADW;
        const int x = p - SW;
        sm[r][p] = ((unsigned)x < (unsigned)W) ? src[r * W + x] : BIG;
    }
    __syncthreads();

    const int r    = threadIdx.x >> 5;
    const int lane = threadIdx.x & 31;
    const int x0   = lane * K;
    const float* row = &sm[r][x0 + SW];       // row[p] == v[x0 + p]

    float acc[K];
    {
        const float4 a = *reinterpret_cast<const float4*>(row);
        const float4 b = *reinterpret_cast<const float4*>(row + 4);
        acc[0] = a.x; acc[1] = a.y; acc[2] = a.z; acc[3] = a.w;
        acc[4] = b.x; acc[5] = b.y; acc[6] = b.z; acc[7] = b.w;
    }

    #pragma unroll
    for (int c = 0; c < NCH; ++c) {
        const int dlo = c * D + 1, dhi = (c + 1) * D;
        float la[4 * NV], ra[4 * NV];
        const float4* lp = reinterpret_cast<const float4*>(row - dhi);
        const float4* rp = reinterpret_cast<const float4*>(row + c * D);
        #pragma unroll
        for (int i = 0; i < NV; ++i) {
            const float4 v = lp[i];
            la[4*i+0] = v.x; la[4*i+1] = v.y; la[4*i+2] = v.z; la[4*i+3] = v.w;
        }
        #pragma unroll
        for (int i = 0; i < NV; ++i) {
            const float4 v = rp[i];
            ra[4*i+0] = v.x; ra[4*i+1] = v.y; ra[4*i+2] = v.z; ra[4*i+3] = v.w;
        }
        #pragma unroll
        for (int d = dlo; d <= dhi; ++d) {
            const float dd = (float)(d * d);              // imm
            #pragma unroll
            for (int k = 0; k < K; ++k) {
                // row[k-d] = la[k+dhi-d]; row[k+d] = ra[k+d-c*D]
                const float m = mm<MX>(la[k + dhi - d], ra[k + d - c * D]);
                acc[k] = mm<MX>(acc[k], fmaf(kcs, dd, m));
            }
        }
    }

    float* dst = out + (long)img * ostr + (long)(rb * ROWS + r) * W + x0;
    #pragma unroll
    for (int k = 0; k < K; ++k) dst[k] = acc[k];
}

// ---------------------------------------------------------------------------
// Vertical pass: block covers 32 cols x 64 output rows; input tile
// (64+2SW) x 32 staged in smem (coalesced loads; compute access sm[y][lane]
// is conflict-free: bank == lane). Chunked sym-pair from smem.
// ---------------------------------------------------------------------------
template<int SW, bool MX>
__global__ void __launch_bounds__(256, 4) vk(
    const float* __restrict__ in,
    float* __restrict__ out, long ostr,
    const float* __restrict__ sc)
{
    constexpr int TR  = 64;                   // output rows per block
    constexpr int TC  = 32;                   // cols per block
    constexpr int SR  = TR + 2 * SW;          // staged rows
    constexpr int D   = (SW < 8) ? SW : 8;
    constexpr int NCH = SW / D;
    constexpr float BIG = MX ? -1e9f : 1e9f;
    const float kc  = (*sc) * (4.0f / (float)(SW * SW));
    const float kcs = MX ? -kc : kc;

    __shared__ float sm[SR][TC];

    const int img = blockIdx.x >> 5;          // 32 tiles per image
    const int t   = blockIdx.x & 31;          // 8 x-tiles x 4 y-tiles
    const int xt  = (t & 7) * TC;
    const int yt  = (t >> 3) * TR;

    const int lane = threadIdx.x & 31;        // column within tile
    const int rg   = threadIdx.x >> 5;        // warp id = row group

    // coalesced stage: warp loads one 32-col row segment per iteration
    const float* src = in + (long)img * NPIX + xt;
    #pragma unroll
    for (int rr = rg; rr < SR; rr += 8) {
        const int y = yt - SW + rr;
        sm[rr][lane] = ((unsigned)y < (unsigned)H) ? src[(long)y * W + lane] : BIG;
    }
    __syncthreads();

    const int b = SW + rg * K;                // smem row of output k=0

    float acc[K];
    #pragma unroll
    for (int k = 0; k < K; ++k) acc[k] = sm[b + k][lane];   // d = 0

    #pragma unroll
    for (int c = 0; c < NCH; ++c) {
        const int dlo = c * D + 1, dhi = (c + 1) * D;
        float L[D + K - 1], R[D + K - 1];
        #pragma unroll
        for (int i = 0; i < D + K - 1; ++i) L[i] = sm[b + i - dhi][lane];
        #pragma unroll
        for (int i = 0; i < D + K - 1; ++i) R[i] = sm[b + i + dlo][lane];
        #pragma unroll
        for (int d = dlo; d <= dhi; ++d) {
            const float dd = (float)(d * d);              // imm
            #pragma unroll
            for (int k = 0; k < K; ++k) {
                const float m = mm<MX>(L[k + dhi - d], R[k + d - dlo]);
                acc[k] = mm<MX>(acc[k], fmaf(kcs, dd, m));
            }
        }
    }

    float* dst = out + (long)img * ostr + (long)(yt + rg * K) * W + xt + lane;
    #pragma unroll
    for (int k = 0; k < K; ++k) dst[(long)k * W] = acc[k];
}

// ---------------------------------------------------------------------------
template<int SW>
static void run_chain(cudaStream_t st, const float* in_p, float* t1_p,
                      float* t2_p, float* out_p, const float* sc)
{
    const int grid = IMGS * 32;               // 1024 blocks, both passes
    hk<SW, true ><<<grid, 256, 0, st>>>(in_p, t1_p, NPIX, sc);
    vk<SW, true ><<<grid, 256, 0, st>>>(t1_p, t2_p, NPIX, sc);
    hk<SW, false><<<grid, 256, 0, st>>>(t2_p, t1_p, NPIX, sc);
    vk<SW, false><<<grid, 256, 0, st>>>(t1_p, out_p, 4L * NPIX, sc);
}

// exact R3 host-object footprint (proved clean vs the mem checker)
static cudaStream_t g_st[3];
static cudaEvent_t  g_fork, g_join[3];
static bool g_ready = false;

extern "C" void kernel_launch(void* const* d_in, const int* in_sizes, int n_in,
                              void* d_out, int out_size)
{
    const float* in = (const float*)d_in[0];
    const float* sc = (const float*)d_in[1];
    if (n_in >= 2 && in_sizes[0] == 1) {      // defensive: order swap
        in = (const float*)d_in[1];
        sc = (const float*)d_in[0];
    }
    float* out = (float*)d_out;

    if (!g_ready) {
        for (int i = 0; i < 3; ++i)
            cudaStreamCreateWithFlags(&g_st[i], cudaStreamNonBlocking);
        cudaEventCreateWithFlags(&g_fork, cudaEventDisableTiming);
        for (int i = 0; i < 3; ++i)
            cudaEventCreateWithFlags(&g_join[i], cudaEventDisableTiming);
        g_ready = true;
    }

    float (*t1)[NTOT] = nullptr;
    float (*t2)[NTOT] = nullptr;
    cudaGetSymbolAddress((void**)&t1, g_t1);
    cudaGetSymbolAddress((void**)&t2, g_t2);

    cudaEventRecord(g_fork, 0);
    for (int i = 0; i < 3; ++i) cudaStreamWaitEvent(g_st[i], g_fork, 0);

    // SW32 (52% of work) on the capture stream; 16/8/4 on side streams
    run_chain<32>(0,       in, t1[3], t2[3], out + 3L * NPIX, sc);
    run_chain<16>(g_st[0], in, t1[2], t2[2], out + 2L * NPIX, sc);
    run_chain< 8>(g_st[1], in, t1[1], t2[1], out + 1L * NPIX, sc);
    run_chain< 4>(g_st[2], in, t1[0], t2[0], out + 0L * NPIX, sc);

    for (int i = 0; i < 3; ++i) {
        cudaEventRecord(g_join[i], g_st[i]);
        cudaStreamWaitEvent(0, g_join[i], 0);
    }

    (void)out_size;
}

// round 7
// speedup vs baseline: 1.3191x; 1.1695x over previous
#include <cuda_runtime.h>

// Multi-scale morphological closing, [4,8,256,256] fp32 -> [4,8,4,256,256].
// closing_s = erosion_s(dilation_s(x)), separable h then v per op.
// SE_s[j] = j^2/(4*t_s), t_s = 4^s, half-width SW_s = 4*2^s, weight se_coef.
// kc = c/(4*t_s) = 4c/SW^2.
//
// Round-7: measured-best hybrid.
//  hk: R3 full-window symmetric-pair (fast in the 97.4us run)
//  vk: R6 smem-tiled chunked symmetric-pair (13.6us, 40 regs) + interior
//      load fast-path + 6 CTA/SM hint
//  streams: R3 3-side-stream fork-join (mem-checker clean)
// Sym-pair identity (bit-exact, rel_err 0.0 since R2):
//   max_j v[x+j]-kc*j^2 = max_d fmaf(-kc, d*d, max(v[x-d], v[x+d]))

namespace {
constexpr int IMGS = 32;     // B*C
constexpr int H    = 256;
constexpr int W    = 256;
constexpr int NPIX = H * W;
constexpr int NTOT = IMGS * NPIX;
constexpr int K    = 8;      // outputs per thread
constexpr int ROWS = 8;      // rows per block, h-pass
}

__device__ float g_t1[4][NTOT];
__device__ float g_t2[4][NTOT];

template<bool MX> __device__ __forceinline__ float mm(float a, float b) {
    return MX ? fmaxf(a, b) : fminf(a, b);
}

// ---------------------------------------------------------------------------
// Horizontal pass (R3 version): block = 256 thr = 8 rows x (32 lanes x 8 out).
// Row staged in smem with sentinel halo; full window in registers (LDS.128).
// ---------------------------------------------------------------------------
template<int SW, bool MX>
__global__ void __launch_bounds__(256) hk(
    const float* __restrict__ in,
    float* __restrict__ out, long ostr,
    const float* __restrict__ sc)
{
    constexpr int PADW = W + 2 * SW;
    constexpr float BIG = MX ? -1e9f : 1e9f;
    const float kc  = (*sc) * (4.0f / (float)(SW * SW));
    const float kcs = MX ? -kc : kc;

    __shared__ __align__(16) float sm[ROWS][PADW];

    const int img = blockIdx.x >> 5;          // 32 row-blocks per image
    const int rb  = blockIdx.x & 31;
    const float* src = in + (long)img * NPIX + (long)(rb * ROWS) * W;

    #pragma unroll
    for (int i = threadIdx.x; i < ROWS * PADW; i += 256) {
        const int r = i / PADW;
        const int p = i - r * PADW;
        const int x = p - SW;
        sm[r][p] = ((unsigned)x < (unsigned)W) ? src[r * W + x] : BIG;
    }
    __syncthreads();

    const int r    = threadIdx.x >> 5;        // warp per row
    const int lane = threadIdx.x & 31;
    const int x0   = lane * K;

    float wv[2 * SW + K];
    const float4* wp = reinterpret_cast<const float4*>(&sm[r][x0]);
    #pragma unroll
    for (int i = 0; i < (2 * SW + K) / 4; ++i) {
        const float4 v = wp[i];
        wv[4 * i + 0] = v.x; wv[4 * i + 1] = v.y;
        wv[4 * i + 2] = v.z; wv[4 * i + 3] = v.w;
    }

    float acc[K];
    #pragma unroll
    for (int k = 0; k < K; ++k) acc[k] = wv[SW + k];      // d = 0

    #pragma unroll
    for (int d = 1; d <= SW; ++d) {
        const float dd = (float)(d * d);                  // imm
        #pragma unroll
        for (int k = 0; k < K; ++k) {
            const float a = wv[SW + k - d], b = wv[SW + k + d];
            const float m = mm<MX>(a, b);
            acc[k] = mm<MX>(acc[k], fmaf(kcs, dd, m));
        }
    }

    float* dst = out + (long)img * ostr + (long)(rb * ROWS + r) * W + x0;
    #pragma unroll
    for (int k = 0; k < K; ++k) dst[k] = acc[k];
}

// ---------------------------------------------------------------------------
// Vertical pass (R6 version + fast-path): block = 32 cols x 64 output rows;
// input tile (64+2SW) x 32 staged in smem (coalesced; compute access
// sm[y][lane] bank-conflict-free). Chunked sym-pair from smem.
// ---------------------------------------------------------------------------
template<int SW, bool MX>
__global__ void __launch_bounds__(256, 6) vk(
    const float* __restrict__ in,
    float* __restrict__ out, long ostr,
    const float* __restrict__ sc)
{
    constexpr int TR  = 64;                   // output rows per block
    constexpr int TC  = 32;                   // cols per block
    constexpr int SR  = TR + 2 * SW;          // staged rows
    constexpr int D   = (SW < 8) ? SW : 8;
    constexpr int NCH = SW / D;
    constexpr float BIG = MX ? -1e9f : 1e9f;
    const float kc  = (*sc) * (4.0f / (float)(SW * SW));
    const float kcs = MX ? -kc : kc;

    __shared__ float sm[SR][TC];

    const int img = blockIdx.x >> 5;          // 32 tiles per image
    const int t   = blockIdx.x & 31;          // 8 x-tiles x 4 y-tiles
    const int xt  = (t & 7) * TC;
    const int yt  = (t >> 3) * TR;

    const int lane = threadIdx.x & 31;        // column within tile
    const int rg   = threadIdx.x >> 5;        // warp id = row group

    const float* src = in + (long)img * NPIX + xt;
    if (yt >= SW && yt + TR + SW <= H) {      // interior: unguarded loads
        #pragma unroll
        for (int rr = rg; rr < SR; rr += 8)
            sm[rr][lane] = src[(long)(yt - SW + rr) * W + lane];
    } else {
        #pragma unroll
        for (int rr = rg; rr < SR; rr += 8) {
            const int y = yt - SW + rr;
            sm[rr][lane] = ((unsigned)y < (unsigned)H) ? src[(long)y * W + lane] : BIG;
        }
    }
    __syncthreads();

    const int b = SW + rg * K;                // smem row of output k=0

    float acc[K];
    #pragma unroll
    for (int k = 0; k < K; ++k) acc[k] = sm[b + k][lane];   // d = 0

    #pragma unroll
    for (int c = 0; c < NCH; ++c) {
        const int dlo = c * D + 1, dhi = (c + 1) * D;
        float L[D + K - 1], R[D + K - 1];
        #pragma unroll
        for (int i = 0; i < D + K - 1; ++i) L[i] = sm[b + i - dhi][lane];
        #pragma unroll
        for (int i = 0; i < D + K - 1; ++i) R[i] = sm[b + i + dlo][lane];
        #pragma unroll
        for (int d = dlo; d <= dhi; ++d) {
            const float dd = (float)(d * d);              // imm
            #pragma unroll
            for (int k = 0; k < K; ++k) {
                const float m = mm<MX>(L[k + dhi - d], R[k + d - dlo]);
                acc[k] = mm<MX>(acc[k], fmaf(kcs, dd, m));
            }
        }
    }

    float* dst = out + (long)img * ostr + (long)(yt + rg * K) * W + xt + lane;
    #pragma unroll
    for (int k = 0; k < K; ++k) dst[(long)k * W] = acc[k];
}

// ---------------------------------------------------------------------------
template<int SW>
static void run_chain(cudaStream_t st, const float* in_p, float* t1_p,
                      float* t2_p, float* out_p, const float* sc)
{
    const int grid = IMGS * 32;               // 1024 blocks, both passes
    hk<SW, true ><<<grid, 256, 0, st>>>(in_p, t1_p, NPIX, sc);
    vk<SW, true ><<<grid, 256, 0, st>>>(t1_p, t2_p, NPIX, sc);
    hk<SW, false><<<grid, 256, 0, st>>>(t2_p, t1_p, NPIX, sc);
    vk<SW, false><<<grid, 256, 0, st>>>(t1_p, out_p, 4L * NPIX, sc);
}

// exact R3 host-object footprint (proved clean vs the mem checker)
static cudaStream_t g_st[3];
static cudaEvent_t  g_fork, g_join[3];
static bool g_ready = false;

extern "C" void kernel_launch(void* const* d_in, const int* in_sizes, int n_in,
                              void* d_out, int out_size)
{
    const float* in = (const float*)d_in[0];
    const float* sc = (const float*)d_in[1];
    if (n_in >= 2 && in_sizes[0] == 1) {      // defensive: order swap
        in = (const float*)d_in[1];
        sc = (const float*)d_in[0];
    }
    float* out = (float*)d_out;

    if (!g_ready) {
        for (int i = 0; i < 3; ++i)
            cudaStreamCreateWithFlags(&g_st[i], cudaStreamNonBlocking);
        cudaEventCreateWithFlags(&g_fork, cudaEventDisableTiming);
        for (int i = 0; i < 3; ++i)
            cudaEventCreateWithFlags(&g_join[i], cudaEventDisableTiming);
        g_ready = true;
    }

    float (*t1)[NTOT] = nullptr;
    float (*t2)[NTOT] = nullptr;
    cudaGetSymbolAddress((void**)&t1, g_t1);
    cudaGetSymbolAddress((void**)&t2, g_t2);

    cudaEventRecord(g_fork, 0);
    for (int i = 0; i < 3; ++i) cudaStreamWaitEvent(g_st[i], g_fork, 0);

    // SW32 (52% of work) on the capture stream; 16/8/4 on side streams
    run_chain<32>(0,       in, t1[3], t2[3], out + 3L * NPIX, sc);
    run_chain<16>(g_st[0], in, t1[2], t2[2], out + 2L * NPIX, sc);
    run_chain< 8>(g_st[1], in, t1[1], t2[1], out + 1L * NPIX, sc);
    run_chain< 4>(g_st[2], in, t1[0], t2[0], out + 0L * NPIX, sc);

    for (int i = 0; i < 3; ++i) {
        cudaEventRecord(g_join[i], g_st[i]);
        cudaStreamWaitEvent(0, g_join[i], 0);
    }

    (void)out_size;
}